// round 15
// baseline (speedup 1.0000x reference)
#include <cuda_runtime.h>
#include <cuda_bf16.h>
#include <math.h>
#include <stdint.h>

// Problem constants
#define T_TOKENS 16384
#define HID      4096
#define NEXP     64
#define TOPK     8
#define RSCALE   2.5f

// Tiling
#define TM    128
#define KBLK  64
#define NKB   (HID / KBLK)
#define NTH   512            // 16 warps: wk = wid&1, wn = (wid>>1)&1, wm = wid>>2

// near-tie refinement threshold (biased-score space)
#define THETA 1.0e-5f
#define NCAND 16             // candidate experts kept per token for exact refinement

// stage layout (bytes): rows 128B, 16B-granule XOR swizzle
#define XHOFF 0
#define XLOFF 16384
#define WHOFF 32768
#define WLOFF 40960
#define STAGE_BYTES 49152
#define SMEM_TOTAL  (2 * STAGE_BYTES)

// epilogue smem offsets (floats within dsm)
#define PARTOFF 0
#define SCOFF   8320

// deterministic per-token refine data (written for every token every launch)
__device__ unsigned char g_flag[T_TOKENS];
__device__ int           g_cand[T_TOKENS][NCAND];

// refine kernel geometry
#define RGRID 592
#define STRIDE_MAX ((T_TOKENS + RGRID - 1) / RGRID)   // 28 tokens per stripe

// ---------------- helpers ----------------
__device__ __forceinline__ uint32_t smem_u32(const void* p) {
    uint32_t a;
    asm("{ .reg .u64 t; cvta.to.shared.u64 t, %1; cvt.u32.u64 %0, t; }" : "=r"(a) : "l"(p));
    return a;
}
__device__ __forceinline__ void ldsm4(uint32_t* r, uint32_t addr) {
    asm volatile("ldmatrix.sync.aligned.m8n8.x4.shared.b16 {%0,%1,%2,%3}, [%4];"
                 : "=r"(r[0]), "=r"(r[1]), "=r"(r[2]), "=r"(r[3]) : "r"(addr));
}
__device__ __forceinline__ void ldsm4t(uint32_t* r, uint32_t addr) {
    asm volatile("ldmatrix.sync.aligned.m8n8.x4.trans.shared.b16 {%0,%1,%2,%3}, [%4];"
                 : "=r"(r[0]), "=r"(r[1]), "=r"(r[2]), "=r"(r[3]) : "r"(addr));
}
__device__ __forceinline__ void mma16816(float* c, const uint32_t* a, uint32_t b0, uint32_t b1) {
    asm volatile(
        "mma.sync.aligned.m16n8k16.row.col.f32.bf16.bf16.f32 "
        "{%0,%1,%2,%3}, {%4,%5,%6,%7}, {%8,%9}, {%0,%1,%2,%3};"
        : "+f"(c[0]), "+f"(c[1]), "+f"(c[2]), "+f"(c[3])
        : "r"(a[0]), "r"(a[1]), "r"(a[2]), "r"(a[3]), "r"(b0), "r"(b1));
}
__device__ __forceinline__ void split2(float f0, float f1, uint32_t& h, uint32_t& l) {
    __nv_bfloat16 h0 = __float2bfloat16_rn(f0);
    __nv_bfloat16 h1 = __float2bfloat16_rn(f1);
    float r0 = __fsub_rn(f0, __bfloat162float(h0));
    float r1 = __fsub_rn(f1, __bfloat162float(h1));
    __nv_bfloat162 hh; hh.x = h0; hh.y = h1;
    __nv_bfloat162 ll; ll.x = __float2bfloat16_rn(r0); ll.y = __float2bfloat16_rn(r1);
    h = *(uint32_t*)&hh;
    l = *(uint32_t*)&ll;
}
__device__ __forceinline__ void split8(float4 a, float4 b, uint4& hi, uint4& lo) {
    split2(a.x, a.y, hi.x, lo.x);
    split2(a.z, a.w, hi.y, lo.y);
    split2(b.x, b.y, hi.z, lo.z);
    split2(b.z, b.w, hi.w, lo.w);
}

// ---------------- gmem load / stage store ----------------
__device__ __forceinline__ void load_gmem(float4* xv, float4* wv, const float* xg,
                                          const float* W, int kb, int tid)
{
    const int k0 = kb * KBLK;
    #pragma unroll
    for (int p = 0; p < 2; ++p) {
        int u   = tid + p * NTH;
        int tok = u >> 3;
        int c8  = (u & 7) * 8;
        const float* src = xg + (size_t)tok * HID + k0 + c8;
        xv[p * 2]     = *(const float4*)(src);
        xv[p * 2 + 1] = *(const float4*)(src + 4);
    }
    {
        int row = tid >> 3;
        int e8  = (tid & 7) * 8;
        const float* src = W + (size_t)(k0 + row) * NEXP + e8;
        wv[0] = *(const float4*)(src);
        wv[1] = *(const float4*)(src + 4);
    }
}
__device__ __forceinline__ void store_stage(char* stage, const float4* xv,
                                            const float4* wv, int tid)
{
    #pragma unroll
    for (int p = 0; p < 2; ++p) {
        int u   = tid + p * NTH;
        int tok = u >> 3;
        int c8  = u & 7;
        uint4 hi, lo;
        split8(xv[p * 2], xv[p * 2 + 1], hi, lo);
        uint32_t off = (uint32_t)tok * 128 + (((uint32_t)c8 * 16) ^ (((uint32_t)tok & 7) << 4));
        *(uint4*)(stage + XHOFF + off) = hi;
        *(uint4*)(stage + XLOFF + off) = lo;
    }
    {
        int row = tid >> 3;
        int u8  = tid & 7;
        uint4 hi, lo;
        split8(wv[0], wv[1], hi, lo);
        uint32_t off = (uint32_t)row * 128 + (((uint32_t)u8 * 16) ^ (((uint32_t)row & 7) << 4));
        *(uint4*)(stage + WHOFF + off) = hi;
        *(uint4*)(stage + WLOFF + off) = lo;
    }
}

// ---------------- kernel 1: MMA gate (byte-identical to R14) ----------------
__global__ __launch_bounds__(NTH, 1)
void moe_gate_mma_kernel(const float* __restrict__ x,
                         const float* __restrict__ W,
                         const float* __restrict__ bias,
                         float* __restrict__ out)
{
    extern __shared__ char dsm[];
    __shared__ float bias_s[NEXP];

    const int tid  = threadIdx.x;
    const int lane = tid & 31;
    const int wid  = tid >> 5;
    const int wk   = wid & 1;
    const int wn   = (wid >> 1) & 1;
    const int wm   = wid >> 2;
    const int t0   = blockIdx.x * TM;
    const float* xg = x + (size_t)t0 * HID;

    if (tid < NEXP) bias_s[tid] = bias[tid];

    float acc[2][4][4];
    #pragma unroll
    for (int m = 0; m < 2; ++m)
        #pragma unroll
        for (int n = 0; n < 4; ++n)
            #pragma unroll
            for (int i = 0; i < 4; ++i) acc[m][n][i] = 0.0f;

    {
        float4 xv[4], wv[2];
        load_gmem(xv, wv, xg, W, 0, tid);
        store_stage(dsm, xv, wv, tid);
    }

    const uint32_t sb0     = smem_u32(dsm);
    const int      tokrow  = wm * 32 + (lane & 15);
    const uint32_t half16  = ((uint32_t)lane >> 4) * 16;
    const uint32_t swA     = ((uint32_t)tokrow & 7) << 4;

    for (int kb = 0; kb < NKB; ++kb) {
        float4 xv[4], wv[2];
        const bool pf = (kb + 1 < NKB);
        if (pf) load_gmem(xv, wv, xg, W, kb + 1, tid);

        __syncthreads();

        const uint32_t sb    = sb0 + (uint32_t)(kb & 1) * STAGE_BYTES;
        const uint32_t aRow0 = sb + XHOFF + (uint32_t)tokrow * 128;
        const uint32_t aRow1 = aRow0 + 16 * 128;

        #pragma unroll
        for (int s = 0; s < 2; ++s) {
            const int sg = wk * 2 + s;
            uint32_t oA = ((uint32_t)(sg * 32) + half16) ^ swA;
            uint32_t aH0[4], aH1[4], aL0[4], aL1[4];
            ldsm4(aH0, aRow0 + oA);
            ldsm4(aH1, aRow1 + oA);
            ldsm4(aL0, aRow0 + (XLOFF - XHOFF) + oA);
            ldsm4(aL1, aRow1 + (XLOFF - XHOFF) + oA);

            const int krow = sg * 16 + (lane & 15);
            const uint32_t swB  = ((uint32_t)krow & 7) << 4;
            const uint32_t bRow = sb + WHOFF + (uint32_t)krow * 128;
            uint32_t oB0 = ((uint32_t)(wn * 64) + half16) ^ swB;
            uint32_t oB1 = ((uint32_t)(wn * 64 + 32) + half16) ^ swB;
            uint32_t bH0[4], bH1[4], bL0[4], bL1[4];
            ldsm4t(bH0, bRow + oB0);
            ldsm4t(bH1, bRow + oB1);
            ldsm4t(bL0, bRow + (WLOFF - WHOFF) + oB0);
            ldsm4t(bL1, bRow + (WLOFF - WHOFF) + oB1);

            #pragma unroll
            for (int m = 0; m < 2; ++m) {
                const uint32_t* aH = m ? aH1 : aH0;
                const uint32_t* aL = m ? aL1 : aL0;
                mma16816(acc[m][0], aH, bH0[0], bH0[1]);
                mma16816(acc[m][1], aH, bH0[2], bH0[3]);
                mma16816(acc[m][2], aH, bH1[0], bH1[1]);
                mma16816(acc[m][3], aH, bH1[2], bH1[3]);
                mma16816(acc[m][0], aH, bL0[0], bL0[1]);
                mma16816(acc[m][1], aH, bL0[2], bL0[3]);
                mma16816(acc[m][2], aH, bL1[0], bL1[1]);
                mma16816(acc[m][3], aH, bL1[2], bL1[3]);
                mma16816(acc[m][0], aL, bH0[0], bH0[1]);
                mma16816(acc[m][1], aL, bH0[2], bH0[3]);
                mma16816(acc[m][2], aL, bH1[0], bH1[1]);
                mma16816(acc[m][3], aL, bH1[2], bH1[3]);
            }
        }

        if (pf)
            store_stage(dsm + ((kb + 1) & 1) * STAGE_BYTES, xv, wv, tid);
    }

    __syncthreads();
    float* smf = (float*)dsm;

    if (wk == 1) {
        #pragma unroll
        for (int m = 0; m < 2; ++m)
            #pragma unroll
            for (int nt = 0; nt < 4; ++nt)
                #pragma unroll
                for (int i = 0; i < 4; ++i) {
                    int row = wm * 32 + m * 16 + (lane >> 2) + ((i >> 1) ? 8 : 0);
                    int col = wn * 32 + nt * 8 + (lane & 3) * 2 + (i & 1);
                    smf[PARTOFF + row * 65 + col] = acc[m][nt][i];
                }
    }
    __syncthreads();
    if (wk == 0) {
        #pragma unroll
        for (int m = 0; m < 2; ++m)
            #pragma unroll
            for (int nt = 0; nt < 4; ++nt)
                #pragma unroll
                for (int i = 0; i < 4; ++i) {
                    int row = wm * 32 + m * 16 + (lane >> 2) + ((i >> 1) ? 8 : 0);
                    int col = wn * 32 + nt * 8 + (lane & 3) * 2 + (i & 1);
                    float l = acc[m][nt][i] + smf[PARTOFF + row * 65 + col];
                    smf[SCOFF + row * 65 + col] = 1.0f / (1.0f + expf(-l));
                }
    }
    __syncthreads();

    if (tid < TM) {
        const int tok = tid;
        const float* sr = smf + SCOFF + tok * 65;
        float bv[NCAND];
        int   bi[NCAND];
        #pragma unroll
        for (int k = 0; k < NCAND; ++k) { bv[k] = -INFINITY; bi[k] = 0; }
        for (int e = 0; e < NEXP; ++e) {
            float sv = sr[e] + bias_s[e];
            if (sv > bv[NCAND - 1]) {
                bv[NCAND - 1] = sv; bi[NCAND - 1] = e;
                #pragma unroll
                for (int j = NCAND - 1; j > 0; --j) {
                    if (bv[j] > bv[j - 1]) {
                        float tv = bv[j]; bv[j] = bv[j - 1]; bv[j - 1] = tv;
                        int   ti = bi[j]; bi[j] = bi[j - 1]; bi[j - 1] = ti;
                    }
                }
            }
        }
        float mingap = INFINITY;
        #pragma unroll
        for (int j = 0; j < 8; ++j) {
            float gp = bv[j] - bv[j + 1];
            if (gp < mingap) mingap = gp;
        }
        const int gtok = t0 + tok;
        g_flag[gtok] = (mingap < THETA) ? 1 : 0;
        #pragma unroll
        for (int j = 0; j < NCAND; ++j) g_cand[gtok][j] = bi[j];

        float wsel[TOPK];
        float sum = 1e-20f;
        #pragma unroll
        for (int k = 0; k < TOPK; ++k) { wsel[k] = sr[bi[k]]; sum += wsel[k]; }
        float inv = RSCALE / sum;
        float* out_idx = out + (size_t)gtok * TOPK;
        float* out_w   = out + (size_t)T_TOKENS * TOPK + (size_t)gtok * TOPK;
        #pragma unroll
        for (int k = 0; k < TOPK; ++k) {
            out_idx[k] = (float)bi[k];
            out_w[k]   = wsel[k] * inv;
        }
    }
}

// ---------------- kernel 2: candidate-set refinement, 2 tokens in flight ----------------
__global__ __launch_bounds__(512, 3)
void refine_kernel(const float* __restrict__ x,
                   const float* __restrict__ W,
                   const float* __restrict__ bias,
                   float* __restrict__ out)
{
    __shared__ double partd[2][16][NCAND];   // [half][kgroup][cand]  4KB
    __shared__ float  sc_s[2][NCAND];
    __shared__ int    cand_s[2][NCAND];
    __shared__ int    loc_list[STRIDE_MAX];
    __shared__ int    loc_cnt;

    const int tid  = threadIdx.x;
    const int half = tid >> 8;            // 0 or 1: independent token slot
    const int htid = tid & 255;
    const int eidx = htid & (NCAND - 1);  // candidate slot 0..15
    const int kg   = htid >> 4;           // k-group 0..15 (256 k each)
    const int barid = 1 + half;           // named barriers 1 and 2

    if (tid == 0) loc_cnt = 0;
    __syncthreads();
    if (tid < STRIDE_MAX) {
        int t = blockIdx.x + tid * RGRID;
        if (t < T_TOKENS && g_flag[t]) {
            int i = atomicAdd(&loc_cnt, 1);
            loc_list[i] = t;
        }
    }
    __syncthreads();
    const int n = loc_cnt;

    // two independent halves, alternate tokens
    for (int it = half; it < n; it += 2) {
        const int tok = loc_list[it];
        if (htid < NCAND) cand_s[half][htid] = g_cand[tok][htid];
        asm volatile("bar.sync %0, 256;" :: "r"(barid) : "memory");

        const int e = cand_s[half][eidx];
        const float* xr = x + (size_t)tok * HID;

        // ILP-2 compensated streams over this thread's 256-k range
        float s0 = 0.0f, c0 = 0.0f, s1 = 0.0f, c1 = 0.0f;
        const int kbeg = kg * 256;
        #pragma unroll
        for (int k = kbeg; k < kbeg + 128; k += 8) {
            const int k2 = k + 128;
            float chA = 0.0f, chB = 0.0f;
            #pragma unroll
            for (int j = 0; j < 8; ++j) {
                chA = __fmaf_rn(xr[k  + j], W[(size_t)(k  + j) * NEXP + e], chA);
                chB = __fmaf_rn(xr[k2 + j], W[(size_t)(k2 + j) * NEXP + e], chB);
            }
            {
                float sp = __fadd_rn(s0, chA);
                float z  = __fsub_rn(sp, s0);
                float e1 = __fsub_rn(chA, z);
                float t2 = __fsub_rn(sp, z);
                float e2 = __fsub_rn(s0, t2);
                c0 = __fadd_rn(c0, __fadd_rn(e1, e2));
                s0 = sp;
            }
            {
                float sp = __fadd_rn(s1, chB);
                float z  = __fsub_rn(sp, s1);
                float e1 = __fsub_rn(chB, z);
                float t2 = __fsub_rn(sp, z);
                float e2 = __fsub_rn(s1, t2);
                c1 = __fadd_rn(c1, __fadd_rn(e1, e2));
                s1 = sp;
            }
        }
        partd[half][kg][eidx] = ((double)s0 + (double)c0) + ((double)s1 + (double)c1);
        asm volatile("bar.sync %0, 256;" :: "r"(barid) : "memory");

        if (htid < NCAND) {
            double l = 0.0;
            #pragma unroll
            for (int g = 0; g < 16; ++g) l += partd[half][g][htid];
            float lf = (float)l;
            sc_s[half][htid] = 1.0f / (1.0f + expf(-lf));
        }
        asm volatile("bar.sync %0, 256;" :: "r"(barid) : "memory");

        if (htid == 0) {
            float bv[TOPK];
            int   bj[TOPK];
            #pragma unroll
            for (int k = 0; k < TOPK; ++k) { bv[k] = -INFINITY; bj[k] = 0; }
            for (int j = 0; j < NCAND; ++j) {
                float sv = sc_s[half][j] + bias[cand_s[half][j]];
                if (sv > bv[TOPK - 1]) {
                    bv[TOPK - 1] = sv; bj[TOPK - 1] = j;
                    #pragma unroll
                    for (int q = TOPK - 1; q > 0; --q) {
                        if (bv[q] > bv[q - 1]) {
                            float tv = bv[q]; bv[q] = bv[q - 1]; bv[q - 1] = tv;
                            int   ti = bj[q]; bj[q] = bj[q - 1]; bj[q - 1] = ti;
                        }
                    }
                }
            }
            float wsel[TOPK];
            float sum = 1e-20f;
            #pragma unroll
            for (int k = 0; k < TOPK; ++k) { wsel[k] = sc_s[half][bj[k]]; sum += wsel[k]; }
            float inv = RSCALE / sum;
            float* out_idx = out + (size_t)tok * TOPK;
            float* out_w   = out + (size_t)T_TOKENS * TOPK + (size_t)tok * TOPK;
            #pragma unroll
            for (int k = 0; k < TOPK; ++k) {
                out_idx[k] = (float)cand_s[half][bj[k]];
                out_w[k]   = wsel[k] * inv;
            }
        }
        asm volatile("bar.sync %0, 256;" :: "r"(barid) : "memory");
    }
}

extern "C" void kernel_launch(void* const* d_in, const int* in_sizes, int n_in,
                              void* d_out, int out_size)
{
    const float* x    = (const float*)d_in[0];
    const float* W    = (const float*)d_in[1];
    const float* bias = (const float*)d_in[2];
    float* out = (float*)d_out;

    cudaFuncSetAttribute(moe_gate_mma_kernel,
                         cudaFuncAttributeMaxDynamicSharedMemorySize, SMEM_TOTAL);

    moe_gate_mma_kernel<<<T_TOKENS / TM, NTH, SMEM_TOTAL>>>(x, W, bias, out);
    refine_kernel<<<RGRID, 512>>>(x, W, bias, out);
}

// round 16
// speedup vs baseline: 1.0443x; 1.0443x over previous
#include <cuda_runtime.h>
#include <cuda_bf16.h>
#include <math.h>
#include <stdint.h>

// Problem constants
#define T_TOKENS 16384
#define HID      4096
#define NEXP     64
#define TOPK     8
#define RSCALE   2.5f

// Tiling
#define TM    128
#define KBLK  64
#define NKB   (HID / KBLK)
#define NTH   512            // 16 warps: wk = wid&1, wn = (wid>>1)&1, wm = wid>>2

// near-tie refinement threshold (biased-score space)
#define THETA 1.0e-5f
#define NCAND 16             // candidate experts kept per token for exact refinement

// stage layout (bytes): rows 128B, 16B-granule XOR swizzle
#define XHOFF 0
#define XLOFF 16384
#define WHOFF 32768
#define WLOFF 40960
#define STAGE_BYTES 49152
#define SMEM_TOTAL  (2 * STAGE_BYTES)

// epilogue smem offsets (floats within dsm)
#define PARTOFF 0
#define SCOFF   8320

// deterministic per-token refine data (written for every token every launch)
__device__ unsigned char g_flag[T_TOKENS];
__device__ int           g_cand[T_TOKENS][NCAND];

// refine kernel geometry: small CTAs, wide grid -> cross-token latency overlap
#define RGRID 2048
#define TPC   (T_TOKENS / RGRID)   // 8 tokens scanned per CTA (stride-interleaved)

// ---------------- helpers ----------------
__device__ __forceinline__ uint32_t smem_u32(const void* p) {
    uint32_t a;
    asm("{ .reg .u64 t; cvta.to.shared.u64 t, %1; cvt.u32.u64 %0, t; }" : "=r"(a) : "l"(p));
    return a;
}
__device__ __forceinline__ void ldsm4(uint32_t* r, uint32_t addr) {
    asm volatile("ldmatrix.sync.aligned.m8n8.x4.shared.b16 {%0,%1,%2,%3}, [%4];"
                 : "=r"(r[0]), "=r"(r[1]), "=r"(r[2]), "=r"(r[3]) : "r"(addr));
}
__device__ __forceinline__ void ldsm4t(uint32_t* r, uint32_t addr) {
    asm volatile("ldmatrix.sync.aligned.m8n8.x4.trans.shared.b16 {%0,%1,%2,%3}, [%4];"
                 : "=r"(r[0]), "=r"(r[1]), "=r"(r[2]), "=r"(r[3]) : "r"(addr));
}
__device__ __forceinline__ void mma16816(float* c, const uint32_t* a, uint32_t b0, uint32_t b1) {
    asm volatile(
        "mma.sync.aligned.m16n8k16.row.col.f32.bf16.bf16.f32 "
        "{%0,%1,%2,%3}, {%4,%5,%6,%7}, {%8,%9}, {%0,%1,%2,%3};"
        : "+f"(c[0]), "+f"(c[1]), "+f"(c[2]), "+f"(c[3])
        : "r"(a[0]), "r"(a[1]), "r"(a[2]), "r"(a[3]), "r"(b0), "r"(b1));
}
__device__ __forceinline__ void split2(float f0, float f1, uint32_t& h, uint32_t& l) {
    __nv_bfloat16 h0 = __float2bfloat16_rn(f0);
    __nv_bfloat16 h1 = __float2bfloat16_rn(f1);
    float r0 = __fsub_rn(f0, __bfloat162float(h0));
    float r1 = __fsub_rn(f1, __bfloat162float(h1));
    __nv_bfloat162 hh; hh.x = h0; hh.y = h1;
    __nv_bfloat162 ll; ll.x = __float2bfloat16_rn(r0); ll.y = __float2bfloat16_rn(r1);
    h = *(uint32_t*)&hh;
    l = *(uint32_t*)&ll;
}
__device__ __forceinline__ void split8(float4 a, float4 b, uint4& hi, uint4& lo) {
    split2(a.x, a.y, hi.x, lo.x);
    split2(a.z, a.w, hi.y, lo.y);
    split2(b.x, b.y, hi.z, lo.z);
    split2(b.z, b.w, hi.w, lo.w);
}

// ---------------- gmem load / stage store ----------------
__device__ __forceinline__ void load_gmem(float4* xv, float4* wv, const float* xg,
                                          const float* W, int kb, int tid)
{
    const int k0 = kb * KBLK;
    #pragma unroll
    for (int p = 0; p < 2; ++p) {
        int u   = tid + p * NTH;
        int tok = u >> 3;
        int c8  = (u & 7) * 8;
        const float* src = xg + (size_t)tok * HID + k0 + c8;
        xv[p * 2]     = *(const float4*)(src);
        xv[p * 2 + 1] = *(const float4*)(src + 4);
    }
    {
        int row = tid >> 3;
        int e8  = (tid & 7) * 8;
        const float* src = W + (size_t)(k0 + row) * NEXP + e8;
        wv[0] = *(const float4*)(src);
        wv[1] = *(const float4*)(src + 4);
    }
}
__device__ __forceinline__ void store_stage(char* stage, const float4* xv,
                                            const float4* wv, int tid)
{
    #pragma unroll
    for (int p = 0; p < 2; ++p) {
        int u   = tid + p * NTH;
        int tok = u >> 3;
        int c8  = u & 7;
        uint4 hi, lo;
        split8(xv[p * 2], xv[p * 2 + 1], hi, lo);
        uint32_t off = (uint32_t)tok * 128 + (((uint32_t)c8 * 16) ^ (((uint32_t)tok & 7) << 4));
        *(uint4*)(stage + XHOFF + off) = hi;
        *(uint4*)(stage + XLOFF + off) = lo;
    }
    {
        int row = tid >> 3;
        int u8  = tid & 7;
        uint4 hi, lo;
        split8(wv[0], wv[1], hi, lo);
        uint32_t off = (uint32_t)row * 128 + (((uint32_t)u8 * 16) ^ (((uint32_t)row & 7) << 4));
        *(uint4*)(stage + WHOFF + off) = hi;
        *(uint4*)(stage + WLOFF + off) = lo;
    }
}

// ---------------- kernel 1: MMA gate (byte-identical to R14) ----------------
__global__ __launch_bounds__(NTH, 1)
void moe_gate_mma_kernel(const float* __restrict__ x,
                         const float* __restrict__ W,
                         const float* __restrict__ bias,
                         float* __restrict__ out)
{
    extern __shared__ char dsm[];
    __shared__ float bias_s[NEXP];

    const int tid  = threadIdx.x;
    const int lane = tid & 31;
    const int wid  = tid >> 5;
    const int wk   = wid & 1;
    const int wn   = (wid >> 1) & 1;
    const int wm   = wid >> 2;
    const int t0   = blockIdx.x * TM;
    const float* xg = x + (size_t)t0 * HID;

    if (tid < NEXP) bias_s[tid] = bias[tid];

    float acc[2][4][4];
    #pragma unroll
    for (int m = 0; m < 2; ++m)
        #pragma unroll
        for (int n = 0; n < 4; ++n)
            #pragma unroll
            for (int i = 0; i < 4; ++i) acc[m][n][i] = 0.0f;

    {
        float4 xv[4], wv[2];
        load_gmem(xv, wv, xg, W, 0, tid);
        store_stage(dsm, xv, wv, tid);
    }

    const uint32_t sb0     = smem_u32(dsm);
    const int      tokrow  = wm * 32 + (lane & 15);
    const uint32_t half16  = ((uint32_t)lane >> 4) * 16;
    const uint32_t swA     = ((uint32_t)tokrow & 7) << 4;

    for (int kb = 0; kb < NKB; ++kb) {
        float4 xv[4], wv[2];
        const bool pf = (kb + 1 < NKB);
        if (pf) load_gmem(xv, wv, xg, W, kb + 1, tid);

        __syncthreads();

        const uint32_t sb    = sb0 + (uint32_t)(kb & 1) * STAGE_BYTES;
        const uint32_t aRow0 = sb + XHOFF + (uint32_t)tokrow * 128;
        const uint32_t aRow1 = aRow0 + 16 * 128;

        #pragma unroll
        for (int s = 0; s < 2; ++s) {
            const int sg = wk * 2 + s;
            uint32_t oA = ((uint32_t)(sg * 32) + half16) ^ swA;
            uint32_t aH0[4], aH1[4], aL0[4], aL1[4];
            ldsm4(aH0, aRow0 + oA);
            ldsm4(aH1, aRow1 + oA);
            ldsm4(aL0, aRow0 + (XLOFF - XHOFF) + oA);
            ldsm4(aL1, aRow1 + (XLOFF - XHOFF) + oA);

            const int krow = sg * 16 + (lane & 15);
            const uint32_t swB  = ((uint32_t)krow & 7) << 4;
            const uint32_t bRow = sb + WHOFF + (uint32_t)krow * 128;
            uint32_t oB0 = ((uint32_t)(wn * 64) + half16) ^ swB;
            uint32_t oB1 = ((uint32_t)(wn * 64 + 32) + half16) ^ swB;
            uint32_t bH0[4], bH1[4], bL0[4], bL1[4];
            ldsm4t(bH0, bRow + oB0);
            ldsm4t(bH1, bRow + oB1);
            ldsm4t(bL0, bRow + (WLOFF - WHOFF) + oB0);
            ldsm4t(bL1, bRow + (WLOFF - WHOFF) + oB1);

            #pragma unroll
            for (int m = 0; m < 2; ++m) {
                const uint32_t* aH = m ? aH1 : aH0;
                const uint32_t* aL = m ? aL1 : aL0;
                mma16816(acc[m][0], aH, bH0[0], bH0[1]);
                mma16816(acc[m][1], aH, bH0[2], bH0[3]);
                mma16816(acc[m][2], aH, bH1[0], bH1[1]);
                mma16816(acc[m][3], aH, bH1[2], bH1[3]);
                mma16816(acc[m][0], aH, bL0[0], bL0[1]);
                mma16816(acc[m][1], aH, bL0[2], bL0[3]);
                mma16816(acc[m][2], aH, bL1[0], bL1[1]);
                mma16816(acc[m][3], aH, bL1[2], bL1[3]);
                mma16816(acc[m][0], aL, bH0[0], bH0[1]);
                mma16816(acc[m][1], aL, bH0[2], bH0[3]);
                mma16816(acc[m][2], aL, bH1[0], bH1[1]);
                mma16816(acc[m][3], aL, bH1[2], bH1[3]);
            }
        }

        if (pf)
            store_stage(dsm + ((kb + 1) & 1) * STAGE_BYTES, xv, wv, tid);
    }

    __syncthreads();
    float* smf = (float*)dsm;

    if (wk == 1) {
        #pragma unroll
        for (int m = 0; m < 2; ++m)
            #pragma unroll
            for (int nt = 0; nt < 4; ++nt)
                #pragma unroll
                for (int i = 0; i < 4; ++i) {
                    int row = wm * 32 + m * 16 + (lane >> 2) + ((i >> 1) ? 8 : 0);
                    int col = wn * 32 + nt * 8 + (lane & 3) * 2 + (i & 1);
                    smf[PARTOFF + row * 65 + col] = acc[m][nt][i];
                }
    }
    __syncthreads();
    if (wk == 0) {
        #pragma unroll
        for (int m = 0; m < 2; ++m)
            #pragma unroll
            for (int nt = 0; nt < 4; ++nt)
                #pragma unroll
                for (int i = 0; i < 4; ++i) {
                    int row = wm * 32 + m * 16 + (lane >> 2) + ((i >> 1) ? 8 : 0);
                    int col = wn * 32 + nt * 8 + (lane & 3) * 2 + (i & 1);
                    float l = acc[m][nt][i] + smf[PARTOFF + row * 65 + col];
                    smf[SCOFF + row * 65 + col] = 1.0f / (1.0f + expf(-l));
                }
    }
    __syncthreads();

    if (tid < TM) {
        const int tok = tid;
        const float* sr = smf + SCOFF + tok * 65;
        float bv[NCAND];
        int   bi[NCAND];
        #pragma unroll
        for (int k = 0; k < NCAND; ++k) { bv[k] = -INFINITY; bi[k] = 0; }
        for (int e = 0; e < NEXP; ++e) {
            float sv = sr[e] + bias_s[e];
            if (sv > bv[NCAND - 1]) {
                bv[NCAND - 1] = sv; bi[NCAND - 1] = e;
                #pragma unroll
                for (int j = NCAND - 1; j > 0; --j) {
                    if (bv[j] > bv[j - 1]) {
                        float tv = bv[j]; bv[j] = bv[j - 1]; bv[j - 1] = tv;
                        int   ti = bi[j]; bi[j] = bi[j - 1]; bi[j - 1] = ti;
                    }
                }
            }
        }
        float mingap = INFINITY;
        #pragma unroll
        for (int j = 0; j < 8; ++j) {
            float gp = bv[j] - bv[j + 1];
            if (gp < mingap) mingap = gp;
        }
        const int gtok = t0 + tok;
        g_flag[gtok] = (mingap < THETA) ? 1 : 0;
        #pragma unroll
        for (int j = 0; j < NCAND; ++j) g_cand[gtok][j] = bi[j];

        float wsel[TOPK];
        float sum = 1e-20f;
        #pragma unroll
        for (int k = 0; k < TOPK; ++k) { wsel[k] = sr[bi[k]]; sum += wsel[k]; }
        float inv = RSCALE / sum;
        float* out_idx = out + (size_t)gtok * TOPK;
        float* out_w   = out + (size_t)T_TOKENS * TOPK + (size_t)gtok * TOPK;
        #pragma unroll
        for (int k = 0; k < TOPK; ++k) {
            out_idx[k] = (float)bi[k];
            out_w[k]   = wsel[k] * inv;
        }
    }
}

// ---------------- kernel 2: candidate-set refinement, small CTAs / wide grid ----------------
__global__ __launch_bounds__(128, 8)
void refine_kernel(const float* __restrict__ x,
                   const float* __restrict__ W,
                   const float* __restrict__ bias,
                   float* __restrict__ out)
{
    __shared__ double partd[8][NCAND];   // [kgroup][cand]  1KB
    __shared__ float  sc_s[NCAND];
    __shared__ int    cand_s[NCAND];
    __shared__ int    loc_list[TPC];
    __shared__ int    loc_cnt;

    const int tid  = threadIdx.x;
    const int eidx = tid & (NCAND - 1);   // candidate slot 0..15
    const int kg   = tid >> 4;            // k-group 0..7 (512 k each)

    if (tid == 0) loc_cnt = 0;
    __syncthreads();
    if (tid < TPC) {
        int t = blockIdx.x + tid * RGRID;
        if (g_flag[t]) {
            int i = atomicAdd(&loc_cnt, 1);
            loc_list[i] = t;
        }
    }
    __syncthreads();
    const int n = loc_cnt;
    if (n == 0) return;   // ~3/4 of CTAs retire immediately

    for (int it = 0; it < n; ++it) {
        const int tok = loc_list[it];
        if (tid < NCAND) cand_s[tid] = g_cand[tok][tid];
        __syncthreads();

        const int e = cand_s[eidx];
        const float* xr = x + (size_t)tok * HID;

        // ILP-2 compensated streams over this thread's 512-k range (chunk-8 + TwoSum)
        float s0 = 0.0f, c0 = 0.0f, s1 = 0.0f, c1 = 0.0f;
        const int kbeg = kg * 512;
        #pragma unroll 4
        for (int k = kbeg; k < kbeg + 256; k += 8) {
            const int k2 = k + 256;
            float chA = 0.0f, chB = 0.0f;
            #pragma unroll
            for (int j = 0; j < 8; ++j) {
                chA = __fmaf_rn(xr[k  + j], W[(size_t)(k  + j) * NEXP + e], chA);
                chB = __fmaf_rn(xr[k2 + j], W[(size_t)(k2 + j) * NEXP + e], chB);
            }
            {
                float sp = __fadd_rn(s0, chA);
                float z  = __fsub_rn(sp, s0);
                float e1 = __fsub_rn(chA, z);
                float t2 = __fsub_rn(sp, z);
                float e2 = __fsub_rn(s0, t2);
                c0 = __fadd_rn(c0, __fadd_rn(e1, e2));
                s0 = sp;
            }
            {
                float sp = __fadd_rn(s1, chB);
                float z  = __fsub_rn(sp, s1);
                float e1 = __fsub_rn(chB, z);
                float t2 = __fsub_rn(sp, z);
                float e2 = __fsub_rn(s1, t2);
                c1 = __fadd_rn(c1, __fadd_rn(e1, e2));
                s1 = sp;
            }
        }
        partd[kg][eidx] = ((double)s0 + (double)c0) + ((double)s1 + (double)c1);
        __syncthreads();

        if (tid < NCAND) {
            double l = 0.0;
            #pragma unroll
            for (int g = 0; g < 8; ++g) l += partd[g][tid];
            float lf = (float)l;
            sc_s[tid] = 1.0f / (1.0f + expf(-lf));
        }
        __syncthreads();

        if (tid == 0) {
            float bv[TOPK];
            int   bj[TOPK];
            #pragma unroll
            for (int k = 0; k < TOPK; ++k) { bv[k] = -INFINITY; bj[k] = 0; }
            for (int j = 0; j < NCAND; ++j) {
                float sv = sc_s[j] + bias[cand_s[j]];
                if (sv > bv[TOPK - 1]) {
                    bv[TOPK - 1] = sv; bj[TOPK - 1] = j;
                    #pragma unroll
                    for (int q = TOPK - 1; q > 0; --q) {
                        if (bv[q] > bv[q - 1]) {
                            float tv = bv[q]; bv[q] = bv[q - 1]; bv[q - 1] = tv;
                            int   ti = bj[q]; bj[q] = bj[q - 1]; bj[q - 1] = ti;
                        }
                    }
                }
            }
            float wsel[TOPK];
            float sum = 1e-20f;
            #pragma unroll
            for (int k = 0; k < TOPK; ++k) { wsel[k] = sc_s[bj[k]]; sum += wsel[k]; }
            float inv = RSCALE / sum;
            float* out_idx = out + (size_t)tok * TOPK;
            float* out_w   = out + (size_t)T_TOKENS * TOPK + (size_t)tok * TOPK;
            #pragma unroll
            for (int k = 0; k < TOPK; ++k) {
                out_idx[k] = (float)cand_s[bj[k]];
                out_w[k]   = wsel[k] * inv;
            }
        }
        __syncthreads();
    }
}

extern "C" void kernel_launch(void* const* d_in, const int* in_sizes, int n_in,
                              void* d_out, int out_size)
{
    const float* x    = (const float*)d_in[0];
    const float* W    = (const float*)d_in[1];
    const float* bias = (const float*)d_in[2];
    float* out = (float*)d_out;

    cudaFuncSetAttribute(moe_gate_mma_kernel,
                         cudaFuncAttributeMaxDynamicSharedMemorySize, SMEM_TOTAL);

    moe_gate_mma_kernel<<<T_TOKENS / TM, NTH, SMEM_TOTAL>>>(x, W, bias, out);
    refine_kernel<<<RGRID, 128>>>(x, W, bias, out);
}

// round 17
// speedup vs baseline: 1.1487x; 1.1000x over previous
#include <cuda_runtime.h>
#include <cuda_bf16.h>
#include <math.h>
#include <stdint.h>

// Problem constants
#define T_TOKENS 16384
#define HID      4096
#define NEXP     64
#define TOPK     8
#define RSCALE   2.5f

// Tiling
#define TM    128
#define KBLK  64
#define NKB   (HID / KBLK)
#define NTH   512            // 16 warps: wk = wid&1, wn = (wid>>1)&1, wm = wid>>2

// near-tie refinement threshold (biased-score space)
#define THETA 1.0e-5f
#define NCAND 16             // candidate experts kept per token for exact refinement

// stage layout (bytes): rows 128B, 16B-granule XOR swizzle
#define XHOFF 0
#define XLOFF 16384
#define WHOFF 32768
#define WLOFF 40960
#define STAGE_BYTES 49152
#define SMEM_TOTAL  (2 * STAGE_BYTES)

// epilogue smem offsets (floats within dsm)
#define PARTOFF 0
#define SCOFF   8320

// compact refine worklist (deterministic SET; self-resetting counter)
__device__ int g_refine_cnt;            // static-init 0; reset at end of refine
__device__ int g_done;                  // arrival ticket
__device__ int g_refine_list[T_TOKENS];
__device__ int g_cand[T_TOKENS][NCAND];

// refine kernel geometry: one wave, 2 CTAs/SM
#define RGRID 296
#define RTH   256

// ---------------- helpers ----------------
__device__ __forceinline__ uint32_t smem_u32(const void* p) {
    uint32_t a;
    asm("{ .reg .u64 t; cvta.to.shared.u64 t, %1; cvt.u32.u64 %0, t; }" : "=r"(a) : "l"(p));
    return a;
}
__device__ __forceinline__ void ldsm4(uint32_t* r, uint32_t addr) {
    asm volatile("ldmatrix.sync.aligned.m8n8.x4.shared.b16 {%0,%1,%2,%3}, [%4];"
                 : "=r"(r[0]), "=r"(r[1]), "=r"(r[2]), "=r"(r[3]) : "r"(addr));
}
__device__ __forceinline__ void ldsm4t(uint32_t* r, uint32_t addr) {
    asm volatile("ldmatrix.sync.aligned.m8n8.x4.trans.shared.b16 {%0,%1,%2,%3}, [%4];"
                 : "=r"(r[0]), "=r"(r[1]), "=r"(r[2]), "=r"(r[3]) : "r"(addr));
}
__device__ __forceinline__ void mma16816(float* c, const uint32_t* a, uint32_t b0, uint32_t b1) {
    asm volatile(
        "mma.sync.aligned.m16n8k16.row.col.f32.bf16.bf16.f32 "
        "{%0,%1,%2,%3}, {%4,%5,%6,%7}, {%8,%9}, {%0,%1,%2,%3};"
        : "+f"(c[0]), "+f"(c[1]), "+f"(c[2]), "+f"(c[3])
        : "r"(a[0]), "r"(a[1]), "r"(a[2]), "r"(a[3]), "r"(b0), "r"(b1));
}
__device__ __forceinline__ void split2(float f0, float f1, uint32_t& h, uint32_t& l) {
    __nv_bfloat16 h0 = __float2bfloat16_rn(f0);
    __nv_bfloat16 h1 = __float2bfloat16_rn(f1);
    float r0 = __fsub_rn(f0, __bfloat162float(h0));
    float r1 = __fsub_rn(f1, __bfloat162float(h1));
    __nv_bfloat162 hh; hh.x = h0; hh.y = h1;
    __nv_bfloat162 ll; ll.x = __float2bfloat16_rn(r0); ll.y = __float2bfloat16_rn(r1);
    h = *(uint32_t*)&hh;
    l = *(uint32_t*)&ll;
}
__device__ __forceinline__ void split8(float4 a, float4 b, uint4& hi, uint4& lo) {
    split2(a.x, a.y, hi.x, lo.x);
    split2(a.z, a.w, hi.y, lo.y);
    split2(b.x, b.y, hi.z, lo.z);
    split2(b.z, b.w, hi.w, lo.w);
}

// ---------------- gmem load / stage store ----------------
__device__ __forceinline__ void load_gmem(float4* xv, float4* wv, const float* xg,
                                          const float* W, int kb, int tid)
{
    const int k0 = kb * KBLK;
    #pragma unroll
    for (int p = 0; p < 2; ++p) {
        int u   = tid + p * NTH;
        int tok = u >> 3;
        int c8  = (u & 7) * 8;
        const float* src = xg + (size_t)tok * HID + k0 + c8;
        xv[p * 2]     = *(const float4*)(src);
        xv[p * 2 + 1] = *(const float4*)(src + 4);
    }
    {
        int row = tid >> 3;
        int e8  = (tid & 7) * 8;
        const float* src = W + (size_t)(k0 + row) * NEXP + e8;
        wv[0] = *(const float4*)(src);
        wv[1] = *(const float4*)(src + 4);
    }
}
__device__ __forceinline__ void store_stage(char* stage, const float4* xv,
                                            const float4* wv, int tid)
{
    #pragma unroll
    for (int p = 0; p < 2; ++p) {
        int u   = tid + p * NTH;
        int tok = u >> 3;
        int c8  = u & 7;
        uint4 hi, lo;
        split8(xv[p * 2], xv[p * 2 + 1], hi, lo);
        uint32_t off = (uint32_t)tok * 128 + (((uint32_t)c8 * 16) ^ (((uint32_t)tok & 7) << 4));
        *(uint4*)(stage + XHOFF + off) = hi;
        *(uint4*)(stage + XLOFF + off) = lo;
    }
    {
        int row = tid >> 3;
        int u8  = tid & 7;
        uint4 hi, lo;
        split8(wv[0], wv[1], hi, lo);
        uint32_t off = (uint32_t)row * 128 + (((uint32_t)u8 * 16) ^ (((uint32_t)row & 7) << 4));
        *(uint4*)(stage + WHOFF + off) = hi;
        *(uint4*)(stage + WLOFF + off) = lo;
    }
}

// ---------------- kernel 1: MMA gate (GEMM byte-identical; epilogue appends worklist) ----------------
__global__ __launch_bounds__(NTH, 1)
void moe_gate_mma_kernel(const float* __restrict__ x,
                         const float* __restrict__ W,
                         const float* __restrict__ bias,
                         float* __restrict__ out)
{
    extern __shared__ char dsm[];
    __shared__ float bias_s[NEXP];

    const int tid  = threadIdx.x;
    const int lane = tid & 31;
    const int wid  = tid >> 5;
    const int wk   = wid & 1;
    const int wn   = (wid >> 1) & 1;
    const int wm   = wid >> 2;
    const int t0   = blockIdx.x * TM;
    const float* xg = x + (size_t)t0 * HID;

    if (tid < NEXP) bias_s[tid] = bias[tid];

    float acc[2][4][4];
    #pragma unroll
    for (int m = 0; m < 2; ++m)
        #pragma unroll
        for (int n = 0; n < 4; ++n)
            #pragma unroll
            for (int i = 0; i < 4; ++i) acc[m][n][i] = 0.0f;

    {
        float4 xv[4], wv[2];
        load_gmem(xv, wv, xg, W, 0, tid);
        store_stage(dsm, xv, wv, tid);
    }

    const uint32_t sb0     = smem_u32(dsm);
    const int      tokrow  = wm * 32 + (lane & 15);
    const uint32_t half16  = ((uint32_t)lane >> 4) * 16;
    const uint32_t swA     = ((uint32_t)tokrow & 7) << 4;

    for (int kb = 0; kb < NKB; ++kb) {
        float4 xv[4], wv[2];
        const bool pf = (kb + 1 < NKB);
        if (pf) load_gmem(xv, wv, xg, W, kb + 1, tid);

        __syncthreads();

        const uint32_t sb    = sb0 + (uint32_t)(kb & 1) * STAGE_BYTES;
        const uint32_t aRow0 = sb + XHOFF + (uint32_t)tokrow * 128;
        const uint32_t aRow1 = aRow0 + 16 * 128;

        #pragma unroll
        for (int s = 0; s < 2; ++s) {
            const int sg = wk * 2 + s;
            uint32_t oA = ((uint32_t)(sg * 32) + half16) ^ swA;
            uint32_t aH0[4], aH1[4], aL0[4], aL1[4];
            ldsm4(aH0, aRow0 + oA);
            ldsm4(aH1, aRow1 + oA);
            ldsm4(aL0, aRow0 + (XLOFF - XHOFF) + oA);
            ldsm4(aL1, aRow1 + (XLOFF - XHOFF) + oA);

            const int krow = sg * 16 + (lane & 15);
            const uint32_t swB  = ((uint32_t)krow & 7) << 4;
            const uint32_t bRow = sb + WHOFF + (uint32_t)krow * 128;
            uint32_t oB0 = ((uint32_t)(wn * 64) + half16) ^ swB;
            uint32_t oB1 = ((uint32_t)(wn * 64 + 32) + half16) ^ swB;
            uint32_t bH0[4], bH1[4], bL0[4], bL1[4];
            ldsm4t(bH0, bRow + oB0);
            ldsm4t(bH1, bRow + oB1);
            ldsm4t(bL0, bRow + (WLOFF - WHOFF) + oB0);
            ldsm4t(bL1, bRow + (WLOFF - WHOFF) + oB1);

            #pragma unroll
            for (int m = 0; m < 2; ++m) {
                const uint32_t* aH = m ? aH1 : aH0;
                const uint32_t* aL = m ? aL1 : aL0;
                mma16816(acc[m][0], aH, bH0[0], bH0[1]);
                mma16816(acc[m][1], aH, bH0[2], bH0[3]);
                mma16816(acc[m][2], aH, bH1[0], bH1[1]);
                mma16816(acc[m][3], aH, bH1[2], bH1[3]);
                mma16816(acc[m][0], aH, bL0[0], bL0[1]);
                mma16816(acc[m][1], aH, bL0[2], bL0[3]);
                mma16816(acc[m][2], aH, bL1[0], bL1[1]);
                mma16816(acc[m][3], aH, bL1[2], bL1[3]);
                mma16816(acc[m][0], aL, bH0[0], bH0[1]);
                mma16816(acc[m][1], aL, bH0[2], bH0[3]);
                mma16816(acc[m][2], aL, bH1[0], bH1[1]);
                mma16816(acc[m][3], aL, bH1[2], bH1[3]);
            }
        }

        if (pf)
            store_stage(dsm + ((kb + 1) & 1) * STAGE_BYTES, xv, wv, tid);
    }

    __syncthreads();
    float* smf = (float*)dsm;

    if (wk == 1) {
        #pragma unroll
        for (int m = 0; m < 2; ++m)
            #pragma unroll
            for (int nt = 0; nt < 4; ++nt)
                #pragma unroll
                for (int i = 0; i < 4; ++i) {
                    int row = wm * 32 + m * 16 + (lane >> 2) + ((i >> 1) ? 8 : 0);
                    int col = wn * 32 + nt * 8 + (lane & 3) * 2 + (i & 1);
                    smf[PARTOFF + row * 65 + col] = acc[m][nt][i];
                }
    }
    __syncthreads();
    if (wk == 0) {
        #pragma unroll
        for (int m = 0; m < 2; ++m)
            #pragma unroll
            for (int nt = 0; nt < 4; ++nt)
                #pragma unroll
                for (int i = 0; i < 4; ++i) {
                    int row = wm * 32 + m * 16 + (lane >> 2) + ((i >> 1) ? 8 : 0);
                    int col = wn * 32 + nt * 8 + (lane & 3) * 2 + (i & 1);
                    float l = acc[m][nt][i] + smf[PARTOFF + row * 65 + col];
                    smf[SCOFF + row * 65 + col] = 1.0f / (1.0f + expf(-l));
                }
    }
    __syncthreads();

    // top-16 per token; append near-ties to compact worklist; tentative outputs
    if (tid < TM) {
        const int tok = tid;
        const float* sr = smf + SCOFF + tok * 65;
        float bv[NCAND];
        int   bi[NCAND];
        #pragma unroll
        for (int k = 0; k < NCAND; ++k) { bv[k] = -INFINITY; bi[k] = 0; }
        for (int e = 0; e < NEXP; ++e) {
            float sv = sr[e] + bias_s[e];
            if (sv > bv[NCAND - 1]) {
                bv[NCAND - 1] = sv; bi[NCAND - 1] = e;
                #pragma unroll
                for (int j = NCAND - 1; j > 0; --j) {
                    if (bv[j] > bv[j - 1]) {
                        float tv = bv[j]; bv[j] = bv[j - 1]; bv[j - 1] = tv;
                        int   ti = bi[j]; bi[j] = bi[j - 1]; bi[j - 1] = ti;
                    }
                }
            }
        }
        float mingap = INFINITY;
        #pragma unroll
        for (int j = 0; j < 8; ++j) {
            float gp = bv[j] - bv[j + 1];
            if (gp < mingap) mingap = gp;
        }
        const int gtok = t0 + tok;
        #pragma unroll
        for (int j = 0; j < NCAND; ++j) g_cand[gtok][j] = bi[j];
        if (mingap < THETA) {
            int idx = atomicAdd(&g_refine_cnt, 1);
            g_refine_list[idx] = gtok;
        }

        float wsel[TOPK];
        float sum = 1e-20f;
        #pragma unroll
        for (int k = 0; k < TOPK; ++k) { wsel[k] = sr[bi[k]]; sum += wsel[k]; }
        float inv = RSCALE / sum;
        float* out_idx = out + (size_t)gtok * TOPK;
        float* out_w   = out + (size_t)T_TOKENS * TOPK + (size_t)gtok * TOPK;
        #pragma unroll
        for (int k = 0; k < TOPK; ++k) {
            out_idx[k] = (float)bi[k];
            out_w[k]   = wsel[k] * inv;
        }
    }
}

// ---------------- kernel 2: compact-worklist exact refinement (one wave) ----------------
__global__ __launch_bounds__(RTH, 2)
void refine_kernel(const float* __restrict__ x,
                   const float* __restrict__ W,
                   const float* __restrict__ bias,
                   float* __restrict__ out)
{
    __shared__ double partd[16][NCAND];   // [kgroup][cand]  2KB
    __shared__ float  sc_s[NCAND];
    __shared__ int    cand_s[NCAND];

    const int tid  = threadIdx.x;
    const int eidx = tid & (NCAND - 1);   // candidate slot 0..15
    const int kg   = tid >> 4;            // k-group 0..15 (256 k each)

    const int n = g_refine_cnt;           // visible: prior kernel completed

    for (int it = blockIdx.x; it < n; it += gridDim.x) {
        const int tok = g_refine_list[it];
        if (tid < NCAND) cand_s[tid] = g_cand[tok][tid];
        __syncthreads();

        const int e = cand_s[eidx];
        const float* xr = x + (size_t)tok * HID;

        // ILP-2 compensated streams over this thread's 256-k range (chunk-8 + TwoSum)
        float s0 = 0.0f, c0 = 0.0f, s1 = 0.0f, c1 = 0.0f;
        const int kbeg = kg * 256;
        #pragma unroll
        for (int k = kbeg; k < kbeg + 128; k += 8) {
            const int k2 = k + 128;
            float chA = 0.0f, chB = 0.0f;
            #pragma unroll
            for (int j = 0; j < 8; ++j) {
                chA = __fmaf_rn(xr[k  + j], W[(size_t)(k  + j) * NEXP + e], chA);
                chB = __fmaf_rn(xr[k2 + j], W[(size_t)(k2 + j) * NEXP + e], chB);
            }
            {
                float sp = __fadd_rn(s0, chA);
                float z  = __fsub_rn(sp, s0);
                float e1 = __fsub_rn(chA, z);
                float t2 = __fsub_rn(sp, z);
                float e2 = __fsub_rn(s0, t2);
                c0 = __fadd_rn(c0, __fadd_rn(e1, e2));
                s0 = sp;
            }
            {
                float sp = __fadd_rn(s1, chB);
                float z  = __fsub_rn(sp, s1);
                float e1 = __fsub_rn(chB, z);
                float t2 = __fsub_rn(sp, z);
                float e2 = __fsub_rn(s1, t2);
                c1 = __fadd_rn(c1, __fadd_rn(e1, e2));
                s1 = sp;
            }
        }
        partd[kg][eidx] = ((double)s0 + (double)c0) + ((double)s1 + (double)c1);
        __syncthreads();

        if (tid < NCAND) {
            double l = 0.0;
            #pragma unroll
            for (int g = 0; g < 16; ++g) l += partd[g][tid];
            float lf = (float)l;
            sc_s[tid] = 1.0f / (1.0f + expf(-lf));
        }
        __syncthreads();

        if (tid == 0) {
            float bv[TOPK];
            int   bj[TOPK];
            #pragma unroll
            for (int k = 0; k < TOPK; ++k) { bv[k] = -INFINITY; bj[k] = 0; }
            for (int j = 0; j < NCAND; ++j) {
                float sv = sc_s[j] + bias[cand_s[j]];
                if (sv > bv[TOPK - 1]) {
                    bv[TOPK - 1] = sv; bj[TOPK - 1] = j;
                    #pragma unroll
                    for (int q = TOPK - 1; q > 0; --q) {
                        if (bv[q] > bv[q - 1]) {
                            float tv = bv[q]; bv[q] = bv[q - 1]; bv[q - 1] = tv;
                            int   ti = bj[q]; bj[q] = bj[q - 1]; bj[q - 1] = ti;
                        }
                    }
                }
            }
            float wsel[TOPK];
            float sum = 1e-20f;
            #pragma unroll
            for (int k = 0; k < TOPK; ++k) { wsel[k] = sc_s[bj[k]]; sum += wsel[k]; }
            float inv = RSCALE / sum;
            float* out_idx = out + (size_t)tok * TOPK;
            float* out_w   = out + (size_t)T_TOKENS * TOPK + (size_t)tok * TOPK;
            #pragma unroll
            for (int k = 0; k < TOPK; ++k) {
                out_idx[k] = (float)cand_s[bj[k]];
                out_w[k]   = wsel[k] * inv;
            }
        }
        __syncthreads();
    }

    // self-reset for next launch/replay (deterministic: last-arriving CTA resets)
    __threadfence();
    if (tid == 0) {
        int d = atomicAdd(&g_done, 1);
        if (d == (int)gridDim.x - 1) {
            g_refine_cnt = 0;
            g_done = 0;
            __threadfence();
        }
    }
}

extern "C" void kernel_launch(void* const* d_in, const int* in_sizes, int n_in,
                              void* d_out, int out_size)
{
    const float* x    = (const float*)d_in[0];
    const float* W    = (const float*)d_in[1];
    const float* bias = (const float*)d_in[2];
    float* out = (float*)d_out;

    cudaFuncSetAttribute(moe_gate_mma_kernel,
                         cudaFuncAttributeMaxDynamicSharedMemorySize, SMEM_TOTAL);

    moe_gate_mma_kernel<<<T_TOKENS / TM, NTH, SMEM_TOTAL>>>(x, W, bias, out);
    refine_kernel<<<RGRID, RTH>>>(x, W, bias, out);
}